// round 13
// baseline (speedup 1.0000x reference)
#include <cuda_runtime.h>
#include <math.h>

// PillarFeatureNet fused — R12: R10 pair-design with native 64-bit shuffles,
// predicate-free even-pair main loop, 56-reg / 9-CTA occupancy target.
// features: (N, 32, 4) f32; num_points: (N,) i32; coors: (N,4) i32 [b,z,cy,cx]
// W: (63,9) f32; gamma/beta/rm/rv: (63,) f32
// out: (N, 64) f32 = [max over points of relu(BN(feats@W^T)) | num_points]

#define MPTS 32
#define WARPS_PER_BLOCK 4
#define THREADS (WARPS_PER_BLOCK * 32)
#define GRID_BLOCKS 1332   // 148 SMs * 9 CTAs

typedef unsigned long long ull;

__device__ __forceinline__ ull fma2(ull a, ull b, ull c) {
    ull d; asm("fma.rn.f32x2 %0,%1,%2,%3;" : "=l"(d) : "l"(a), "l"(b), "l"(c)); return d;
}
__device__ __forceinline__ ull mul2(ull a, ull b) {
    ull d; asm("mul.rn.f32x2 %0,%1,%2;" : "=l"(d) : "l"(a), "l"(b)); return d;
}
__device__ __forceinline__ ull add2(ull a, ull b) {
    ull d; asm("add.rn.f32x2 %0,%1,%2;" : "=l"(d) : "l"(a), "l"(b)); return d;
}
__device__ __forceinline__ ull sub2(ull a, ull b) {
    ull d; asm("sub.rn.f32x2 %0,%1,%2;" : "=l"(d) : "l"(a), "l"(b)); return d;
}
__device__ __forceinline__ ull dup2(float v) {
    ull d; asm("mov.b64 %0,{%1,%1};" : "=l"(d) : "f"(v)); return d;
}
__device__ __forceinline__ ull pack2(float lo, float hi) {
    ull d; asm("mov.b64 %0,{%1,%2};" : "=l"(d) : "f"(lo), "f"(hi)); return d;
}
__device__ __forceinline__ float2 unpk(ull p) {
    float lo, hi; asm("mov.b64 {%0,%1},%2;" : "=f"(lo), "=f"(hi) : "l"(p));
    return make_float2(lo, hi);
}

__global__ __launch_bounds__(THREADS, 9)
void pfn_kernel(const float4* __restrict__ feats,
                const int*    __restrict__ num_points,
                const int*    __restrict__ coors,      // (N,4) ints; [2]=cy,[3]=cx
                const float*  __restrict__ W,
                const float*  __restrict__ gma,
                const float*  __restrict__ bta,
                const float*  __restrict__ rmean,
                const float*  __restrict__ rvar,
                float* __restrict__ out, int N)
{
    constexpr float VX = 0.16f, VY = 0.16f;
    constexpr float X_OFF = 0.08f;       // VX/2 + 0.0
    constexpr float Y_OFF = -39.6f;      // VY/2 + (-39.68)
    constexpr float BN_EPS = 1e-3f;

    __shared__ float  sbuf[WARPS_PER_BLOCK][4][2][MPTS];   // two-pillar SoA staging
    __shared__ float2 swm[5][32];        // swm[k][lane] = {wm_k(2l), wm_k(2l+1)}

    const int lane = threadIdx.x & 31;
    const int warp = threadIdx.x >> 5;
    const int uA = 2 * lane;             // outputs uA, uA+1 (lane31: 62, col63=np)
    const bool haveB = (uA + 1) < 63;

    // ---- fold weights + BN (ws packed in regs; wm in shared) ----
    ull wsa0, wsa1, wsa2, wsa3;
    ull wsb0 = 0, wsb1 = 0, wsb2 = 0, wsb3 = 0;
    float ba, bb = 0.f;
    {
        const float inv = gma[uA] * rsqrtf(rvar[uA] + BN_EPS);
        ba = bta[uA] - rmean[uA] * inv;
        const float* w = W + uA * 9;
        wsa0 = dup2((w[0] + w[4] + w[7]) * inv);
        wsa1 = dup2((w[1] + w[5] + w[8]) * inv);
        wsa2 = dup2((w[2] + w[6]) * inv);
        wsa3 = dup2(w[3] * inv);
        if (warp == 0) {
            #pragma unroll
            for (int k = 0; k < 5; ++k) swm[k][lane].x = w[4 + k] * inv;
        }
    }
    if (haveB) {
        const int uB = uA + 1;
        const float inv = gma[uB] * rsqrtf(rvar[uB] + BN_EPS);
        bb = bta[uB] - rmean[uB] * inv;
        const float* w = W + uB * 9;
        wsb0 = dup2((w[0] + w[4] + w[7]) * inv);
        wsb1 = dup2((w[1] + w[5] + w[8]) * inv);
        wsb2 = dup2((w[2] + w[6]) * inv);
        wsb3 = dup2(w[3] * inv);
        if (warp == 0) {
            #pragma unroll
            for (int k = 0; k < 5; ++k) swm[k][lane].y = w[4 + k] * inv;
        }
    } else if (warp == 0) {
        #pragma unroll
        for (int k = 0; k < 5; ++k) swm[k][lane].y = 0.f;
    }
    const ull bap = pack2(ba, bb);
    __syncthreads();

    const float nanv = __int_as_float(0x7fffffff);   // qNaN: dropped by fmaxf
    const int gw = blockIdx.x * WARPS_PER_BLOCK + warp;
    const int nwarps = gridDim.x * WARPS_PER_BLOCK;
    const int pstride = 2 * nwarps;
    const int Neven = N & ~1;            // main loop handles full pairs only

    int n0 = 2 * gw;
    if (n0 < Neven) {
        // ---- prime: load pair 0 (both pillars guaranteed valid) ----
        float4 f0 = __ldcs(&feats[(size_t)n0 * MPTS + lane]);
        float4 f1 = __ldcs(&feats[(size_t)(n0 + 1) * MPTS + lane]);
        int2 np01 = *(const int2*)(num_points + n0);             // n0 even: aligned
        int2 cz0 = *(const int2*)(coors + (size_t)n0 * 4 + 2);   // {cy,cx}
        int2 cz1 = *(const int2*)(coors + (size_t)(n0 + 1) * 4 + 2);

        while (true) {
            const int n_nx = n0 + pstride;
            const bool have_next = (n_nx < Neven);
            const int np0 = np01.x, np1 = np01.y;

            // packed cross-pillar butterfly over ALL 32 raw points (native ull shfl)
            ull X01 = pack2(f0.x, f1.x);
            ull Y01 = pack2(f0.y, f1.y);
            ull Z01 = pack2(f0.z, f1.z);
            #pragma unroll
            for (int off = 16; off; off >>= 1) {
                X01 = add2(X01, __shfl_xor_sync(0xffffffffu, X01, off));
                Y01 = add2(Y01, __shfl_xor_sync(0xffffffffu, Y01, off));
                Z01 = add2(Z01, __shfl_xor_sync(0xffffffffu, Z01, off));
            }
            const float2 sx = unpk(X01), sy = unpk(Y01), sz = unpk(Z01);

            // stage both pillars (NaN in padded slots)
            __syncwarp();                    // prior iteration's reads done
            const bool v0 = lane < np0, v1 = lane < np1;
            sbuf[warp][0][0][lane] = v0 ? f0.x : nanv;
            sbuf[warp][1][0][lane] = v0 ? f0.y : nanv;
            sbuf[warp][2][0][lane] = v0 ? f0.z : nanv;
            sbuf[warp][3][0][lane] = v0 ? f0.w : nanv;
            sbuf[warp][0][1][lane] = v1 ? f1.x : nanv;
            sbuf[warp][1][1][lane] = v1 ? f1.y : nanv;
            sbuf[warp][2][1][lane] = v1 ? f1.z : nanv;
            sbuf[warp][3][1][lane] = v1 ? f1.w : nanv;

            // register-neutral prefetch of the NEXT pair
            int2 np_nx, cz0_nx, cz1_nx;
            if (have_next) {
                f0 = __ldcs(&feats[(size_t)n_nx * MPTS + lane]);
                f1 = __ldcs(&feats[(size_t)(n_nx + 1) * MPTS + lane]);
                np_nx  = *(const int2*)(num_points + n_nx);
                cz0_nx = *(const int2*)(coors + (size_t)n_nx * 4 + 2);
                cz1_nx = *(const int2*)(coors + (size_t)(n_nx + 1) * 4 + 2);
            }

            // per-pillar packed constants {c(uA), c(uA+1)}
            const ull m0 = *(const ull*)&swm[0][lane];
            const ull m1 = *(const ull*)&swm[1][lane];
            const ull m2 = *(const ull*)&swm[2][lane];
            const ull m3 = *(const ull*)&swm[3][lane];
            const ull m4 = *(const ull*)&swm[4][lane];

            const float rnp0 = __fdividef(1.0f, (float)np0);
            ull t0 = mul2(m0, dup2(sx.x * rnp0));
            t0 = fma2(m1, dup2(sy.x * rnp0), t0);
            t0 = fma2(m2, dup2(sz.x * rnp0), t0);
            t0 = fma2(m3, dup2((float)cz0.y * VX + X_OFF), t0);
            t0 = fma2(m4, dup2((float)cz0.x * VY + Y_OFF), t0);
            const float2 cp0 = unpk(sub2(bap, t0));

            const float rnp1 = __fdividef(1.0f, (float)np1);
            ull t1 = mul2(m0, dup2(sx.y * rnp1));
            t1 = fma2(m1, dup2(sy.y * rnp1), t1);
            t1 = fma2(m2, dup2(sz.y * rnp1), t1);
            t1 = fma2(m3, dup2((float)cz1.y * VX + X_OFF), t1);
            t1 = fma2(m4, dup2((float)cz1.x * VY + Y_OFF), t1);
            const float2 cp1 = unpk(sub2(bap, t1));

            __syncwarp();                    // staging visible

            // ---- pillar 0 ----
            {
                const ulonglong2* X2 = (const ulonglong2*)sbuf[warp][0][0];
                const ulonglong2* Y2 = (const ulonglong2*)sbuf[warp][1][0];
                const ulonglong2* Z2 = (const ulonglong2*)sbuf[warp][2][0];
                const ulonglong2* W2 = (const ulonglong2*)sbuf[warp][3][0];
                float r0 = -INFINITY, r1 = -INFINITY;
                #pragma unroll
                for (int c = 0; c < MPTS / 4; ++c) {
                    if (c == 0 || np0 > 4 * c) {
                        const ulonglong2 X = X2[c], Y = Y2[c], Z = Z2[c], Wv = W2[c];
                        const ull qA0 = fma2(X.x, wsa0, fma2(Y.x, wsa1, fma2(Z.x, wsa2, mul2(Wv.x, wsa3))));
                        const ull qA1 = fma2(X.y, wsa0, fma2(Y.y, wsa1, fma2(Z.y, wsa2, mul2(Wv.y, wsa3))));
                        const ull qB0 = fma2(X.x, wsb0, fma2(Y.x, wsb1, fma2(Z.x, wsb2, mul2(Wv.x, wsb3))));
                        const ull qB1 = fma2(X.y, wsb0, fma2(Y.y, wsb1, fma2(Z.y, wsb2, mul2(Wv.y, wsb3))));
                        const float2 a0 = unpk(qA0), a1 = unpk(qA1);
                        const float2 b0 = unpk(qB0), b1 = unpk(qB1);
                        r0 = fmaxf(r0, fmaxf(fmaxf(a0.x, a0.y), fmaxf(a1.x, a1.y)));
                        r1 = fmaxf(r1, fmaxf(fmaxf(b0.x, b0.y), fmaxf(b1.x, b1.y)));
                    }
                }
                float d0 = r0 + cp0.x, d1 = r1 + cp0.y;
                if (np0 < MPTS) { d0 = fmaxf(d0, ba); d1 = fmaxf(d1, bb); }
                float2 val;
                val.x = fmaxf(d0, 0.0f);
                val.y = haveB ? fmaxf(d1, 0.0f) : (float)np0;
                __stcs((float2*)out + (size_t)n0 * 32 + lane, val);
            }

            // ---- pillar 1 ----
            {
                const ulonglong2* X2 = (const ulonglong2*)sbuf[warp][0][1];
                const ulonglong2* Y2 = (const ulonglong2*)sbuf[warp][1][1];
                const ulonglong2* Z2 = (const ulonglong2*)sbuf[warp][2][1];
                const ulonglong2* W2 = (const ulonglong2*)sbuf[warp][3][1];
                float r0 = -INFINITY, r1 = -INFINITY;
                #pragma unroll
                for (int c = 0; c < MPTS / 4; ++c) {
                    if (c == 0 || np1 > 4 * c) {
                        const ulonglong2 X = X2[c], Y = Y2[c], Z = Z2[c], Wv = W2[c];
                        const ull qA0 = fma2(X.x, wsa0, fma2(Y.x, wsa1, fma2(Z.x, wsa2, mul2(Wv.x, wsa3))));
                        const ull qA1 = fma2(X.y, wsa0, fma2(Y.y, wsa1, fma2(Z.y, wsa2, mul2(Wv.y, wsa3))));
                        const ull qB0 = fma2(X.x, wsb0, fma2(Y.x, wsb1, fma2(Z.x, wsb2, mul2(Wv.x, wsb3))));
                        const ull qB1 = fma2(X.y, wsb0, fma2(Y.y, wsb1, fma2(Z.y, wsb2, mul2(Wv.y, wsb3))));
                        const float2 a0 = unpk(qA0), a1 = unpk(qA1);
                        const float2 b0 = unpk(qB0), b1 = unpk(qB1);
                        r0 = fmaxf(r0, fmaxf(fmaxf(a0.x, a0.y), fmaxf(a1.x, a1.y)));
                        r1 = fmaxf(r1, fmaxf(fmaxf(b0.x, b0.y), fmaxf(b1.x, b1.y)));
                    }
                }
                float d0 = r0 + cp1.x, d1 = r1 + cp1.y;
                if (np1 < MPTS) { d0 = fmaxf(d0, ba); d1 = fmaxf(d1, bb); }
                float2 val;
                val.x = fmaxf(d0, 0.0f);
                val.y = haveB ? fmaxf(d1, 0.0f) : (float)np1;
                __stcs((float2*)out + (size_t)(n0 + 1) * 32 + lane, val);
            }

            if (!have_next) break;
            n0 = n_nx; np01 = np_nx; cz0 = cz0_nx; cz1 = cz1_nx;
        }
    }

    // odd-N straggler pillar (dead for N=120000; handled by global warp 0)
    if ((N & 1) && gw == 0) {
        const int n = N - 1;
        const float4 f = feats[(size_t)n * MPTS + lane];
        const int np = num_points[n];
        const int2 cz = *(const int2*)(coors + (size_t)n * 4 + 2);
        float sxs = f.x, sys = f.y, szs = f.z;
        #pragma unroll
        for (int off = 16; off; off >>= 1) {
            sxs += __shfl_xor_sync(0xffffffffu, sxs, off);
            sys += __shfl_xor_sync(0xffffffffu, sys, off);
            szs += __shfl_xor_sync(0xffffffffu, szs, off);
        }
        __syncwarp();
        const bool v = lane < np;
        sbuf[warp][0][0][lane] = v ? f.x : nanv;
        sbuf[warp][1][0][lane] = v ? f.y : nanv;
        sbuf[warp][2][0][lane] = v ? f.z : nanv;
        sbuf[warp][3][0][lane] = v ? f.w : nanv;
        const float rnp = __fdividef(1.0f, (float)np);
        const ull m0 = *(const ull*)&swm[0][lane];
        const ull m1 = *(const ull*)&swm[1][lane];
        const ull m2 = *(const ull*)&swm[2][lane];
        const ull m3 = *(const ull*)&swm[3][lane];
        const ull m4 = *(const ull*)&swm[4][lane];
        ull t = mul2(m0, dup2(sxs * rnp));
        t = fma2(m1, dup2(sys * rnp), t);
        t = fma2(m2, dup2(szs * rnp), t);
        t = fma2(m3, dup2((float)cz.y * VX + X_OFF), t);
        t = fma2(m4, dup2((float)cz.x * VY + Y_OFF), t);
        const float2 cp = unpk(sub2(bap, t));
        __syncwarp();
        const ulonglong2* X2 = (const ulonglong2*)sbuf[warp][0][0];
        const ulonglong2* Y2 = (const ulonglong2*)sbuf[warp][1][0];
        const ulonglong2* Z2 = (const ulonglong2*)sbuf[warp][2][0];
        const ulonglong2* W2 = (const ulonglong2*)sbuf[warp][3][0];
        float r0 = -INFINITY, r1 = -INFINITY;
        #pragma unroll
        for (int c = 0; c < MPTS / 4; ++c) {
            if (c == 0 || np > 4 * c) {
                const ulonglong2 X = X2[c], Y = Y2[c], Z = Z2[c], Wv = W2[c];
                const ull qA0 = fma2(X.x, wsa0, fma2(Y.x, wsa1, fma2(Z.x, wsa2, mul2(Wv.x, wsa3))));
                const ull qA1 = fma2(X.y, wsa0, fma2(Y.y, wsa1, fma2(Z.y, wsa2, mul2(Wv.y, wsa3))));
                const ull qB0 = fma2(X.x, wsb0, fma2(Y.x, wsb1, fma2(Z.x, wsb2, mul2(Wv.x, wsb3))));
                const ull qB1 = fma2(X.y, wsb0, fma2(Y.y, wsb1, fma2(Z.y, wsb2, mul2(Wv.y, wsb3))));
                const float2 a0 = unpk(qA0), a1 = unpk(qA1);
                const float2 b0 = unpk(qB0), b1 = unpk(qB1);
                r0 = fmaxf(r0, fmaxf(fmaxf(a0.x, a0.y), fmaxf(a1.x, a1.y)));
                r1 = fmaxf(r1, fmaxf(fmaxf(b0.x, b0.y), fmaxf(b1.x, b1.y)));
            }
        }
        float d0 = r0 + cp.x, d1 = r1 + cp.y;
        if (np < MPTS) { d0 = fmaxf(d0, ba); d1 = fmaxf(d1, bb); }
        float2 val;
        val.x = fmaxf(d0, 0.0f);
        val.y = haveB ? fmaxf(d1, 0.0f) : (float)np;
        __stcs((float2*)out + (size_t)n * 32 + lane, val);
    }
}

extern "C" void kernel_launch(void* const* d_in, const int* in_sizes, int n_in,
                              void* d_out, int out_size)
{
    const float* features  = (const float*)d_in[0];
    const int*   num_pts   = (const int*)  d_in[1];
    const int*   coors     = (const int*)  d_in[2];
    const float* W         = (const float*)d_in[3];
    const float* gma       = (const float*)d_in[4];
    const float* bta       = (const float*)d_in[5];
    const float* rmean     = (const float*)d_in[6];
    const float* rvar      = (const float*)d_in[7];

    int N = in_sizes[1];                     // num_points element count == N pillars
    if (N <= 0 || N != in_sizes[0] / (MPTS * 4)) {
        N = in_sizes[0] / (MPTS * 4);        // defensive fallback
    }

    pfn_kernel<<<GRID_BLOCKS, THREADS>>>(
        (const float4*)features, num_pts, coors,
        W, gma, bta, rmean, rvar, (float*)d_out, N);
}